// round 4
// baseline (speedup 1.0000x reference)
#include <cuda_runtime.h>
#include <math.h>

// Problem constants (from reference)
#define Bn    16
#define Tn    512
#define Dn    256
#define Vn    4233
#define LMAXn 64
#define Sn    129          // 2*LMAX+1 extended states
#define NLAB  65           // blank + LMAX distinct label slots per batch
#define BT    (Bn * Tn)    // 8192 rows
#define NCT   34           // ceil(Vn / 128) column tiles
#define NEGF  (-1e30f)

// ---- device scratch (allocation-free rule: static __device__ arrays) ----
__device__ float g_psum[NCT * BT];            // per-coltile partial sum(exp(logit))
__device__ float g_lse[BT];                   // log(sum(exp(logit))) per (b,t)
__device__ float g_lab[Bn * Tn * NLAB];       // raw logits at blank + labels
__device__ float g_ll[Bn];                    // per-batch log-likelihood

// ============================================================
// Kernel A: label logits (raw). Block = (b, 8 t's), 8 warps, one t per warp.
// lab[b][t][0]  = <hs, W[0]> + bias[0]            (blank)
// lab[b][t][li] = <hs, W[ys[li-1]]> + bias[...]   (li = 1..64)
// ============================================================
__global__ __launch_bounds__(256) void ka_label_logits(
    const float* __restrict__ hs, const float* __restrict__ W,
    const float* __restrict__ bias, const int* __restrict__ ys_pad)
{
    __shared__ float hs_s[8][256];
    __shared__ float wsh[256];
    int b   = blockIdx.y;
    int t0  = blockIdx.x * 8;
    int tid = threadIdx.x;
    int w    = tid >> 5;
    int lane = tid & 31;

    // cooperative load of 8 hs rows (8*256 floats) as float4
    const float4* hsg  = (const float4*)(hs + (size_t)(b * Tn + t0) * Dn);
    float4*       hss4 = (float4*)&hs_s[0][0];
    hss4[tid]       = hsg[tid];
    hss4[tid + 256] = hsg[tid + 256];

    float* outrow = g_lab + (size_t)(b * Tn + t0 + w) * NLAB;

    for (int li = 0; li < NLAB; li++) {
        int lab = (li == 0) ? 0 : ys_pad[b * LMAXn + li - 1];
        wsh[tid] = W[(size_t)lab * Dn + tid];
        __syncthreads();
        float partial = 0.f;
        #pragma unroll
        for (int i = 0; i < 8; i++)
            partial += hs_s[w][lane + 32 * i] * wsh[lane + 32 * i];
        #pragma unroll
        for (int d = 16; d >= 1; d >>= 1)
            partial += __shfl_xor_sync(0xffffffffu, partial, d);
        if (lane == 0) {
            outrow[li] = partial + bias[lab];
        }
        __syncthreads();
    }
}

// ============================================================
// Kernel B: tiled SGEMM 128x128xK256 with fused sum(exp(logit+bias)) epilogue.
// Grid (34 col tiles, 64 row tiles), 256 threads, 8x8 per-thread tile.
// Writes g_psum[ct][row]; combined later. No logits hit HBM.
// ============================================================
__global__ __launch_bounds__(256) void kb_gemm_sumexp(
    const float* __restrict__ hs, const float* __restrict__ W,
    const float* __restrict__ bias)
{
    __shared__ float As[8][128];
    __shared__ float Bs[8][128];
    int ct = blockIdx.x, rt = blockIdx.y;
    int r0 = rt * 128, c0 = ct * 128;
    int tid = threadIdx.x;

    int lr = tid >> 1;            // 0..127: row (A) / col (B) within tile
    int lk = (tid & 1) * 4;       // 0 or 4: k quad within the 8-wide slab
    const float* Ap = hs + (size_t)(r0 + lr) * Dn + lk;
    int colB = c0 + lr;
    bool colv = colB < Vn;
    const float* Bp = W + (size_t)(colv ? colB : 0) * Dn + lk;

    int tx = tid & 15, ty = tid >> 4;

    float acc[8][8];
    #pragma unroll
    for (int i = 0; i < 8; i++)
        #pragma unroll
        for (int j = 0; j < 8; j++) acc[i][j] = 0.f;

    float4 ra = *(const float4*)Ap;
    float4 rb = colv ? *(const float4*)Bp : make_float4(0.f, 0.f, 0.f, 0.f);

    #pragma unroll 1
    for (int kt = 0; kt < 32; kt++) {
        As[lk + 0][lr] = ra.x; As[lk + 1][lr] = ra.y;
        As[lk + 2][lr] = ra.z; As[lk + 3][lr] = ra.w;
        Bs[lk + 0][lr] = rb.x; Bs[lk + 1][lr] = rb.y;
        Bs[lk + 2][lr] = rb.z; Bs[lk + 3][lr] = rb.w;
        __syncthreads();

        if (kt < 31) {   // register prefetch of next K slab
            ra = *(const float4*)(Ap + (kt + 1) * 8);
            rb = colv ? *(const float4*)(Bp + (kt + 1) * 8)
                      : make_float4(0.f, 0.f, 0.f, 0.f);
        }

        #pragma unroll
        for (int k = 0; k < 8; k++) {
            float af[8], bf[8];
            *(float4*)&af[0] = *(const float4*)&As[k][ty * 8];
            *(float4*)&af[4] = *(const float4*)&As[k][ty * 8 + 4];
            *(float4*)&bf[0] = *(const float4*)&Bs[k][tx * 8];
            *(float4*)&bf[4] = *(const float4*)&Bs[k][tx * 8 + 4];
            #pragma unroll
            for (int i = 0; i < 8; i++)
                #pragma unroll
                for (int j = 0; j < 8; j++)
                    acc[i][j] = fmaf(af[i], bf[j], acc[i][j]);
        }
        __syncthreads();
    }

    // epilogue: add bias, sum exp over this tile's 128 cols, reduce across tx
    float bj[8]; bool cv[8];
    #pragma unroll
    for (int j = 0; j < 8; j++) {
        int c = c0 + tx * 8 + j;
        cv[j] = c < Vn;
        bj[j] = cv[j] ? bias[c] : 0.f;
    }
    #pragma unroll
    for (int i = 0; i < 8; i++) {
        float rs = 0.f;
        #pragma unroll
        for (int j = 0; j < 8; j++)
            if (cv[j]) rs += __expf(acc[i][j] + bj[j]);
        rs += __shfl_xor_sync(0xffffffffu, rs, 1);
        rs += __shfl_xor_sync(0xffffffffu, rs, 2);
        rs += __shfl_xor_sync(0xffffffffu, rs, 4);
        rs += __shfl_xor_sync(0xffffffffu, rs, 8);
        if (tx == 0) g_psum[ct * BT + r0 + ty * 8 + i] = rs;
    }
}

// ============================================================
// Kernel C: combine partials -> log-sum-exp per row
// ============================================================
__global__ void kc_lse()
{
    int r = blockIdx.x * blockDim.x + threadIdx.x;
    if (r < BT) {
        float s = 0.f;
        #pragma unroll
        for (int ct = 0; ct < NCT; ct++) s += g_psum[ct * BT + r];
        g_lse[r] = logf(s);
    }
}

// ============================================================
// Kernel D: CTC forward DP in LOG domain (numerically safe).
// One warp per batch. State layout: s = lane + 32*j, j=0..4 (S=129).
// Neighbor exchange via shuffles only; no barriers.
// ============================================================
__global__ __launch_bounds__(32) void kd_ctc_dp(
    const int* __restrict__ hlens, const int* __restrict__ ys_pad,
    const int* __restrict__ ys_lens)
{
    const unsigned FULL = 0xffffffffu;
    int b    = blockIdx.x;
    int lane = threadIdx.x;

    // allow[s] = (s odd, s>=3) && y_k != y_{k-1}, k=(s-1)/2
    bool allow[5];
    #pragma unroll
    for (int j = 0; j < 5; j++) {
        int s = lane + 32 * j;
        bool al = false;
        if (s < Sn && (s & 1) && s >= 2) {
            int k = (s - 1) >> 1;   // >= 1 since s >= 3
            al = (ys_pad[b * LMAXn + k] != ys_pad[b * LMAXn + k - 1]);
        }
        allow[j] = al;
    }

    const float* lb   = g_lab + (size_t)b * Tn * NLAB;
    const float* lseb = g_lse + b * Tn;

    float a[5] = {NEGF, NEGF, NEGF, NEGF, NEGF};
    {   // t = 0: alpha[0]=lp(blank), alpha[1]=lp(y_1)
        float lse0 = lseb[0];
        if (lane == 0) a[0] = lb[0] - lse0;
        if (lane == 1) a[0] = lb[1] - lse0;
    }
    int hlen = hlens[b];

    // prefetch logits for t=1
    float pn[5];
    float lsen = lseb[1];
    #pragma unroll
    for (int j = 0; j < 5; j++) {
        int s = lane + 32 * j;
        pn[j] = (s < Sn) ? lb[NLAB + ((s & 1) ? (s >> 1) + 1 : 0)] : 0.f;
    }

    for (int t = 1; t < Tn; t++) {
        float lg[5]; float lse = lsen;
        #pragma unroll
        for (int j = 0; j < 5; j++) lg[j] = pn[j];
        if (t + 1 < Tn) {           // software prefetch next frame
            lsen = lseb[t + 1];
            const float* lp = lb + (size_t)(t + 1) * NLAB;
            #pragma unroll
            for (int j = 0; j < 5; j++) {
                int s = lane + 32 * j;
                pn[j] = (s < Sn) ? lp[(s & 1) ? (s >> 1) + 1 : 0] : 0.f;
            }
        }

        float prev31 = NEGF, prev30 = NEGF;  // lanes 31/30 of previous chunk
        float nv[5];
        #pragma unroll
        for (int j = 0; j < 5; j++) {
            float u1  = __shfl_up_sync(FULL, a[j], 1);
            float u2  = __shfl_up_sync(FULL, a[j], 2);
            float b31 = __shfl_sync(FULL, a[j], 31);
            float b30 = __shfl_sync(FULL, a[j], 30);
            float am1 = (lane >= 1) ? u1 : prev31;
            float am2 = (lane >= 2) ? u2 : ((lane == 1) ? prev31 : prev30);
            float a2m = allow[j] ? am2 : NEGF;
            // logaddexp3 in log domain
            float m  = fmaxf(fmaxf(a[j], am1), a2m);
            float sm = __expf(a[j] - m) + __expf(am1 - m) + __expf(a2m - m);
            nv[j] = m + __logf(sm) + (lg[j] - lse);
            prev31 = b31; prev30 = b30;
        }
        if (t < hlen) {
            #pragma unroll
            for (int j = 0; j < 5; j++) a[j] = nv[j];
        }
    }

    int last = 2 * ys_lens[b];
    int jl = last >> 5,        ll2 = last & 31;
    int jp = (last - 1) >> 5,  lp2 = (last - 1) & 31;
    float vl = NEGF, vp = NEGF;
    #pragma unroll
    for (int j = 0; j < 5; j++) {
        float t1 = __shfl_sync(FULL, a[j], ll2);
        float t2 = __shfl_sync(FULL, a[j], lp2);
        if (j == jl) vl = t1;
        if (j == jp) vp = t2;
    }
    if (lane == 0) {
        float m = fmaxf(vl, vp);
        g_ll[b] = m + __logf(__expf(vl - m) + __expf(vp - m));
    }
}

// ============================================================
// Kernel E: loss = -sum(ll)/B
// ============================================================
__global__ void ke_final(float* __restrict__ out)
{
    int lane = threadIdx.x;
    float v = (lane < Bn) ? g_ll[lane] : 0.f;
    #pragma unroll
    for (int d = 16; d >= 1; d >>= 1)
        v += __shfl_xor_sync(0xffffffffu, v, d);
    if (lane == 0) out[0] = -v / (float)Bn;
}

// ============================================================
extern "C" void kernel_launch(void* const* d_in, const int* in_sizes, int n_in,
                              void* d_out, int out_size)
{
    const float* hs      = (const float*)d_in[0];   // [B,T,D] f32
    const int*   hlens   = (const int*)d_in[1];     // [B] i32
    const int*   ys_pad  = (const int*)d_in[2];     // [B,LMAX] i32
    const int*   ys_lens = (const int*)d_in[3];     // [B] i32
    const float* W       = (const float*)d_in[4];   // [V,D] f32
    const float* bias    = (const float*)d_in[5];   // [V] f32
    float*       out     = (float*)d_out;           // scalar f32

    ka_label_logits<<<dim3(Tn / 8, Bn), 256>>>(hs, W, bias, ys_pad);
    kb_gemm_sumexp<<<dim3(NCT, BT / 128), 256>>>(hs, W, bias);
    kc_lse<<<32, 256>>>();
    kd_ctc_dp<<<Bn, 32>>>(hlens, ys_pad, ys_lens);
    ke_final<<<1, 32>>>(out);
}